// round 2
// baseline (speedup 1.0000x reference)
#include <cuda_runtime.h>
#include <math.h>

#define Bn 32
#define Tn 512
#define Hn 2048
#define Kn 128

// Scratch (no allocations allowed)
__device__ float g_logits[Bn * Tn * Kn];   // 8 MB
__device__ float g_llh[Bn];

typedef unsigned long long ull;

// ---- f32x2 helpers (Blackwell packed fp32; each half bit-identical to scalar)
__device__ __forceinline__ ull pack2(float lo, float hi) {
    ull r; asm("mov.b64 %0, {%1,%2};" : "=l"(r) : "f"(lo), "f"(hi)); return r;
}
__device__ __forceinline__ float2 unpack2(ull v) {
    float2 f; asm("mov.b64 {%0,%1}, %2;" : "=f"(f.x), "=f"(f.y) : "l"(v)); return f;
}
__device__ __forceinline__ ull ffma2(ull a, ull b, ull c) {
    ull d; asm("fma.rn.f32x2 %0, %1, %2, %3;" : "=l"(d) : "l"(a), "l"(b), "l"(c));
    return d;
}
__device__ __forceinline__ ull fadd2(ull a, ull b) {
    ull d; asm("add.rn.f32x2 %0, %1, %2;" : "=l"(d) : "l"(a), "l"(b)); return d;
}

// ---------------------------------------------------------------------------
// GEMM: logits = hiddens @ W + b.  M=16384, N=128, H=2048.
// BM=64, BN=128, BK=16, 256 threads. FFMA2 over row-pairs: per-output
// accumulation order identical to scalar version (bit-identical logits).
// ---------------------------------------------------------------------------
__global__ __launch_bounds__(256) void gemm_kernel(
    const float* __restrict__ hid, const float* __restrict__ W,
    const float* __restrict__ bias)
{
    __shared__ float As[16][64];    // transposed: As[k][m]
    __shared__ float Bs[16][128];

    const int tid = threadIdx.x;
    const int m0  = blockIdx.x * 64;
    const int ty  = tid >> 5;       // 0..7 row group (8 rows)
    const int tx  = tid & 31;       // 0..31 col group (4 cols)

    ull acc2[4][4];                 // [row-pair q][col jj]
#pragma unroll
    for (int q = 0; q < 4; q++)
#pragma unroll
        for (int jj = 0; jj < 4; jj++) acc2[q][jj] = 0ULL;

    const int arow = tid >> 2;            // 0..63
    const int ac4  = (tid & 3) * 4;       // 0,4,8,12

    for (int k0 = 0; k0 < Hn; k0 += 16) {
        float4 a4 = *(const float4*)(hid + (size_t)(m0 + arow) * Hn + k0 + ac4);
        As[ac4 + 0][arow] = a4.x;
        As[ac4 + 1][arow] = a4.y;
        As[ac4 + 2][arow] = a4.z;
        As[ac4 + 3][arow] = a4.w;
        {
            int idx = tid;
            int r = idx >> 5, c = (idx & 31) * 4;
            *(float4*)(&Bs[r][c]) = *(const float4*)(W + (size_t)(k0 + r) * Kn + c);
            idx = tid + 256;
            r = idx >> 5; c = (idx & 31) * 4;
            *(float4*)(&Bs[r][c]) = *(const float4*)(W + (size_t)(k0 + r) * Kn + c);
        }
        __syncthreads();

#pragma unroll
        for (int k = 0; k < 16; k++) {
            float4 b4 = *(const float4*)(&Bs[k][tx * 4]);
            ull b2[4];
            b2[0] = pack2(b4.x, b4.x);
            b2[1] = pack2(b4.y, b4.y);
            b2[2] = pack2(b4.z, b4.z);
            b2[3] = pack2(b4.w, b4.w);
            ull a2[4];
#pragma unroll
            for (int q = 0; q < 4; q++)
                a2[q] = *(const ull*)(&As[k][ty * 8 + 2 * q]);
#pragma unroll
            for (int q = 0; q < 4; q++) {
                acc2[q][0] = ffma2(a2[q], b2[0], acc2[q][0]);
                acc2[q][1] = ffma2(a2[q], b2[1], acc2[q][1]);
                acc2[q][2] = ffma2(a2[q], b2[2], acc2[q][2]);
                acc2[q][3] = ffma2(a2[q], b2[3], acc2[q][3]);
            }
        }
        __syncthreads();
    }

    const int n0 = tx * 4;
    float4 bb = *(const float4*)(bias + n0);
#pragma unroll
    for (int q = 0; q < 4; q++) {
        float2 c0 = unpack2(acc2[q][0]);
        float2 c1 = unpack2(acc2[q][1]);
        float2 c2 = unpack2(acc2[q][2]);
        float2 c3 = unpack2(acc2[q][3]);
        int r0 = m0 + ty * 8 + 2 * q;
        float4 o;
        o.x = c0.x + bb.x; o.y = c1.x + bb.y; o.z = c2.x + bb.z; o.w = c3.x + bb.w;
        *(float4*)(g_logits + (size_t)r0 * Kn + n0) = o;
        o.x = c0.y + bb.x; o.y = c1.y + bb.y; o.z = c2.y + bb.z; o.w = c3.y + bb.w;
        *(float4*)(g_logits + (size_t)(r0 + 1) * Kn + n0) = o;
    }
}

// ---------------------------------------------------------------------------
// CRF kernel. 64 blocks x 256 threads.
// blocks [0,32): forward logsumexp + path score -> g_llh[b]
// blocks [32,64): viterbi -> out tags
// j = tid>>1 (tag column), h = tid&1 (row half of 64).
// Shared layout (bytes):
//   [0,1024)      : double-buffered score/p vectors  sbuf[2][128]
//   [1024,1032)   : msh[2]   (shift per buffer)
//   [1032,1040)   : sa0[2]   (thread0 alpha per buffer)
//   [1056,1088)   : shred[8] floats
//   [1088,1120)   : shredi[8] ints
//   [1152,1664)   : sfin[128]
//   [1664,67072)  : bp[511*128] bytes (viterbi backpointers)
// ---------------------------------------------------------------------------
#define SMEM_BYTES (1664 + (Tn - 1) * Kn)

__global__ __launch_bounds__(256) void crf_kernel(
    const int* __restrict__ mask, const int* __restrict__ labels,
    const float* __restrict__ startT, const float* __restrict__ endT,
    const float* __restrict__ trans, float* __restrict__ out)
{
    extern __shared__ char smem[];
    float (*sbuf)[Kn] = (float(*)[Kn])smem;
    float* msh   = (float*)(smem + 1024);
    float* sa0   = (float*)(smem + 1032);
    float* shred = (float*)(smem + 1056);
    int*  shredi = (int*)(smem + 1088);
    float* sfin  = (float*)(smem + 1152);
    unsigned char* bp = (unsigned char*)(smem + 1664);

    const int tid = threadIdx.x;
    const int j = tid >> 1, h = tid & 1;
    const unsigned FULL = 0xFFFFFFFFu;
    const int bidx = blockIdx.x;

    if (bidx < Bn) {
        // ================= FORWARD =================
        const int b = bidx;
        // E2[q] = (exp(T[h*64+2q][j]), exp(T[h*64+2q+1][j]))
        ull E2[32];
#pragma unroll
        for (int q = 0; q < 32; q++) {
            int i0 = h * 64 + 2 * q;
            E2[q] = pack2(expf(trans[i0 * Kn + j]),
                          expf(trans[(i0 + 1) * Kn + j]));
        }

        const float* lg = g_logits + (size_t)b * Tn * Kn;
        float alpha = startT[j] + lg[j];
        // initial shift: alpha_0, computable by every thread
        float M0 = startT[0] + lg[0];
        if (h == 0) sbuf[0][j] = expf(alpha - M0);
        if (tid == 0) { msh[0] = M0; sa0[0] = alpha; }
        float e_next = lg[Kn + j];
        __syncthreads();

        for (int t = 1; t < Tn; t++) {
            const int cur = (t - 1) & 1, nbuf = t & 1;
            float M  = msh[cur];
            float A0 = sa0[cur];
            float emit = e_next;
            if (t + 1 < Tn) e_next = lg[(size_t)(t + 1) * Kn + j];
            int mt = mask[b * Tn + t];

            ull s2 = 0ULL;
            const ulonglong2* pv = (const ulonglong2*)(&sbuf[cur][h * 64]);
#pragma unroll
            for (int q = 0; q < 16; q++) {
                ulonglong2 v = pv[q];
                s2 = ffma2(v.x, E2[2 * q],     s2);
                s2 = ffma2(v.y, E2[2 * q + 1], s2);
            }
            float2 sf = unpack2(s2);
            float s = sf.x + sf.y;
            s += __shfl_xor_sync(FULL, s, 1);

            float nxt = M + logf(s) + emit;
            alpha = (mt > 0) ? nxt : alpha;

            // new shift = previous-step alpha_0 (bounded near current alphas)
            float Mn = A0;
            if (h == 0) sbuf[nbuf][j] = expf(alpha - Mn);
            if (tid == 0) { msh[nbuf] = Mn; sa0[nbuf] = alpha; }
            __syncthreads();
        }

        // logZ = logsumexp_j(alpha_j + end_j)  (off critical path; exact reduce)
        float v = alpha + endT[j];
        float wm = v;
#pragma unroll
        for (int o = 16; o; o >>= 1)
            wm = fmaxf(wm, __shfl_xor_sync(FULL, wm, o));
        if ((tid & 31) == 0) shred[tid >> 5] = wm;
        __syncthreads();
        float m = shred[0];
#pragma unroll
        for (int w = 1; w < 8; w++) m = fmaxf(m, shred[w]);
        __syncthreads();
        float pc = (h == 0) ? expf(v - m) : 0.f;
#pragma unroll
        for (int o = 16; o; o >>= 1)
            pc += __shfl_xor_sync(FULL, pc, o);
        if ((tid & 31) == 0) shred[tid >> 5] = pc;
        __syncthreads();
        float Z = 0.f;
#pragma unroll
        for (int w = 0; w < 8; w++) Z += shred[w];
        float logZ = m + logf(Z);
        __syncthreads();

        // path score
        float sc = 0.f;
        int msum = 0;
        for (int t = tid; t < Tn; t += 256) {
            msum += mask[b * Tn + t];
            if (t >= 1) {
                int cur  = labels[b * Tn + t];
                int prev = labels[b * Tn + t - 1];
                float mf = (float)mask[b * Tn + t];
                sc += (trans[prev * Kn + cur] + lg[(size_t)t * Kn + cur]) * mf;
            }
        }
#pragma unroll
        for (int o = 16; o; o >>= 1) {
            sc   += __shfl_xor_sync(FULL, sc, o);
            msum += __shfl_xor_sync(FULL, msum, o);
        }
        if ((tid & 31) == 0) { shred[tid >> 5] = sc; shredi[tid >> 5] = msum; }
        __syncthreads();
        if (tid == 0) {
            float S = 0.f; int Mc = 0;
#pragma unroll
            for (int w = 0; w < 8; w++) { S += shred[w]; Mc += shredi[w]; }
            int l0 = labels[b * Tn];
            S += startT[l0] + lg[l0];
            int last = labels[b * Tn + (Mc - 1)];
            S += endT[last];
            g_llh[b] = S - logZ;
        }
    } else {
        // ================= VITERBI =================
        const int b = bidx - Bn;
        // T2[r] = (T[h*64+2r][j], T[h*64+2r+1][j])
        ull T2[32];
#pragma unroll
        for (int r = 0; r < 32; r++) {
            int i0 = h * 64 + 2 * r;
            T2[r] = pack2(trans[i0 * Kn + j], trans[(i0 + 1) * Kn + j]);
        }

        const float* lg = g_logits + (size_t)b * Tn * Kn;
        float sj = startT[j] + lg[j];
        if (h == 0) sbuf[0][j] = sj;
        float e_next = lg[Kn + j];
        __syncthreads();

        for (int t = 1; t < Tn; t++) {
            const int cur = (t - 1) & 1, nbuf = t & 1;
            float emit = e_next;
            if (t + 1 < Tn) e_next = lg[(size_t)(t + 1) * Kn + j];
            int mt = mask[b * Tn + t];

            const ulonglong2* s4 = (const ulonglong2*)(&sbuf[cur][h * 64]);
            float best = -3.4e38f;
            int bg = 0;
            // 8 groups of 8 candidates; value-max with group tracking
#pragma unroll
            for (int g = 0; g < 8; g++) {
                ulonglong2 u0 = s4[2 * g];
                ulonglong2 u1 = s4[2 * g + 1];
                float2 c0 = unpack2(fadd2(u0.x, T2[4 * g + 0]));
                float2 c1 = unpack2(fadd2(u0.y, T2[4 * g + 1]));
                float2 c2 = unpack2(fadd2(u1.x, T2[4 * g + 2]));
                float2 c3 = unpack2(fadd2(u1.y, T2[4 * g + 3]));
                float m01 = fmaxf(c0.x, c0.y);
                float m23 = fmaxf(c1.x, c1.y);
                float m45 = fmaxf(c2.x, c2.y);
                float m67 = fmaxf(c3.x, c3.y);
                float gmax = fmaxf(fmaxf(m01, m23), fmaxf(m45, m67));
                if (gmax > best) { best = gmax; bg = g; }  // ties -> first group
            }
            // recompute winner group, find first index equal to best (exact)
            {
                ulonglong2 w0 = s4[2 * bg];
                ulonglong2 w1 = s4[2 * bg + 1];
                float2 c0 = unpack2(fadd2(w0.x, T2[4 * bg + 0]));
                float2 c1 = unpack2(fadd2(w0.y, T2[4 * bg + 1]));
                float2 c2 = unpack2(fadd2(w1.x, T2[4 * bg + 2]));
                float2 c3 = unpack2(fadd2(w1.y, T2[4 * bg + 3]));
                float cc[8] = {c0.x, c0.y, c1.x, c1.y, c2.x, c2.y, c3.x, c3.y};
                int aq = 0;
#pragma unroll
                for (int q = 7; q >= 0; q--)      // descending: first match wins
                    if (cc[q] == best) aq = q;
                int ai = h * 64 + bg * 8 + aq;

                // cross-h combine; h==0 wins ties (lower global index)
                float ob = __shfl_xor_sync(FULL, best, 1);
                int   oi = __shfl_xor_sync(FULL, ai, 1);
                float lb = (h == 0) ? best : ob;
                int   li = (h == 0) ? ai   : oi;
                float hb = (h == 0) ? ob   : best;
                int   hi = (h == 0) ? oi   : ai;
                float fb; int fa;
                if (hb > lb) { fb = hb; fa = hi; } else { fb = lb; fa = li; }

                float ns; int bpv;
                if (mt > 0) { ns = fb + emit; bpv = fa; }
                else        { ns = sj;        bpv = j;  }
                sj = ns;
                if (h == 0) {
                    sbuf[nbuf][j] = sj;
                    bp[(size_t)(t - 1) * Kn + j] = (unsigned char)bpv;
                }
            }
            __syncthreads();
        }

        if (h == 0) sfin[j] = sj + endT[j];
        __syncthreads();
        if (tid == 0) {
            float bbest = sfin[0];
            int btag = 0;
            for (int q = 1; q < Kn; q++) {
                float vv = sfin[q];
                if (vv > bbest) { bbest = vv; btag = q; }
            }
            int tag = btag;
            out[b * Tn + (Tn - 1)] = (float)tag;
            for (int t = Tn - 2; t >= 0; t--) {
                tag = bp[(size_t)t * Kn + tag];
                out[b * Tn + t] = (float)tag;
            }
        }
    }
}

// ---------------------------------------------------------------------------
// loss = -mean(llh)
// ---------------------------------------------------------------------------
__global__ void loss_kernel(float* __restrict__ out)
{
    const unsigned FULL = 0xFFFFFFFFu;
    float v = (threadIdx.x < Bn) ? g_llh[threadIdx.x] : 0.f;
#pragma unroll
    for (int o = 16; o; o >>= 1) v += __shfl_xor_sync(FULL, v, o);
    if (threadIdx.x == 0) out[Bn * Tn] = -(v / (float)Bn);
}

extern "C" void kernel_launch(void* const* d_in, const int* in_sizes, int n_in,
                              void* d_out, int out_size)
{
    const float* hiddens = (const float*)d_in[0];
    const int*   mask    = (const int*)d_in[1];
    const int*   labels  = (const int*)d_in[2];
    const float* W       = (const float*)d_in[3];
    const float* bias    = (const float*)d_in[4];
    const float* startT  = (const float*)d_in[5];
    const float* endT    = (const float*)d_in[6];
    const float* trans   = (const float*)d_in[7];
    float* out = (float*)d_out;

    gemm_kernel<<<(Bn * Tn) / 64, 256>>>(hiddens, W, bias);

    cudaFuncSetAttribute(crf_kernel, cudaFuncAttributeMaxDynamicSharedMemorySize,
                         SMEM_BYTES);
    crf_kernel<<<2 * Bn, 256, SMEM_BYTES>>>(mask, labels, startT, endT, trans, out);

    loss_kernel<<<1, 32>>>(out);
}

// round 4
// speedup vs baseline: 1.1146x; 1.1146x over previous
#include <cuda_runtime.h>
#include <math.h>

#define Bn 32
#define Tn 512
#define Hn 2048
#define Kn 128

#define NGEMM  232            // persistent GEMM worker blocks
#define NTILES 512            // 8 chunks * (32 batches * 2 half-tiles)
#define TPC    64             // tiles per time-chunk

// Scratch (no allocations allowed)
__device__ float g_logits[Bn * Tn * Kn];   // 8 MB
__device__ float g_llh[Bn];
__device__ int   g_cnt[8];                 // tiles completed per chunk
__device__ int   g_ticket;                 // GEMM work ticket

// smem: [0,512) sh_s | [512,768) shred | [768,1024) shredi | [1024,..) bp
// GEMM view: [0,2048) As | [2048,10240) Bs | [10240,10244) sh_tk
#define SMEM_BYTES (1024 + (Tn - 1) * Kn)

__global__ void init_kernel()
{
    if (threadIdx.x < 8) g_cnt[threadIdx.x] = 0;
    if (threadIdx.x == 0) g_ticket = 0;
}

__device__ __forceinline__ void wait_chunk(int c, int tid)
{
    if (tid == 0) {
        while (atomicAdd(&g_cnt[c], 0) < TPC) { }
    }
    __syncthreads();
    __threadfence();
}

// ---------------------------------------------------------------------------
// Fused kernel. 296 blocks x 256 threads.
//   bids [0,32)    : forward logsumexp + path score -> g_llh[b]
//   bids [32,64)   : viterbi decode -> out tags
//   bids [64,296)  : persistent GEMM workers (ticket, time-chunk-major tiles)
// ---------------------------------------------------------------------------
__global__ __launch_bounds__(256) void fused_kernel(
    const float* __restrict__ hid, const float* __restrict__ W,
    const float* __restrict__ bias,
    const int* __restrict__ mask, const int* __restrict__ labels,
    const float* __restrict__ startT, const float* __restrict__ endT,
    const float* __restrict__ trans, float* __restrict__ out)
{
    extern __shared__ char smem[];
    const int tid  = threadIdx.x;
    const int bidx = blockIdx.x;
    const unsigned FULL = 0xFFFFFFFFu;

    if (bidx >= 2 * Bn) {
        // ================= GEMM workers =================
        // tile = 32 rows (time) x 128 cols (tags), BK=16, 256 threads,
        // 4x4 outputs/thread. Accumulation order identical to R1 (bit-exact).
        float* As    = (float*)smem;             // [16][32]
        float* Bs    = (float*)(smem + 2048);    // [16][128]
        int*   sh_tk = (int*)(smem + 10240);

        const int ty4  = (tid >> 5) * 4;   // row offset in tile
        const int tx   = tid & 31;         // col group
        const int arow = tid >> 3;         // 0..31
        const int ac2  = (tid & 7) * 2;    // 0,2,..,14

        for (;;) {
            if (tid == 0) *sh_tk = atomicAdd(&g_ticket, 1);
            __syncthreads();
            const int tk = *sh_tk;
            __syncthreads();
            if (tk >= NTILES) break;

            const int c    = tk >> 6;          // time chunk 0..7
            const int ii   = tk & 63;
            const int b    = ii >> 1;
            const int half = ii & 1;
            const int m0   = b * Tn + c * 64 + half * 32;

            float acc[4][4];
#pragma unroll
            for (int r = 0; r < 4; r++)
#pragma unroll
                for (int q = 0; q < 4; q++) acc[r][q] = 0.f;

            const float* Arow = hid + (size_t)(m0 + arow) * Hn + ac2;

            for (int k0 = 0; k0 < Hn; k0 += 16) {
                float2 a2 = *(const float2*)(Arow + k0);
                As[(ac2 + 0) * 32 + arow] = a2.x;
                As[(ac2 + 1) * 32 + arow] = a2.y;
                {
                    int r  = tid >> 5;
                    int c4 = (tid & 31) * 4;
                    *(float4*)(Bs + r * 128 + c4) =
                        *(const float4*)(W + (size_t)(k0 + r) * Kn + c4);
                    r += 8;
                    *(float4*)(Bs + r * 128 + c4) =
                        *(const float4*)(W + (size_t)(k0 + r) * Kn + c4);
                }
                __syncthreads();
#pragma unroll
                for (int k = 0; k < 16; k++) {
                    float4 b4 = *(const float4*)(Bs + k * 128 + tx * 4);
                    float4 a4 = *(const float4*)(As + k * 32 + ty4);
                    acc[0][0] += a4.x * b4.x; acc[0][1] += a4.x * b4.y;
                    acc[0][2] += a4.x * b4.z; acc[0][3] += a4.x * b4.w;
                    acc[1][0] += a4.y * b4.x; acc[1][1] += a4.y * b4.y;
                    acc[1][2] += a4.y * b4.z; acc[1][3] += a4.y * b4.w;
                    acc[2][0] += a4.z * b4.x; acc[2][1] += a4.z * b4.y;
                    acc[2][2] += a4.z * b4.z; acc[2][3] += a4.z * b4.w;
                    acc[3][0] += a4.w * b4.x; acc[3][1] += a4.w * b4.y;
                    acc[3][2] += a4.w * b4.z; acc[3][3] += a4.w * b4.w;
                }
                __syncthreads();
            }

            const int n0 = tx * 4;
            float4 bb = *(const float4*)(bias + n0);
#pragma unroll
            for (int r = 0; r < 4; r++) {
                float4 o;
                o.x = acc[r][0] + bb.x;
                o.y = acc[r][1] + bb.y;
                o.z = acc[r][2] + bb.z;
                o.w = acc[r][3] + bb.w;
                *(float4*)(g_logits + (size_t)(m0 + ty4 + r) * Kn + n0) = o;
            }
            __threadfence();
            __syncthreads();
            if (tid == 0) atomicAdd(&g_cnt[c], 1);
        }
        return;
    }

    // ================= CRF =================
    float* sh_s   = (float*)smem;                 // 128 floats
    float* shred  = (float*)(smem + 512);
    int*   shredi = (int*)(smem + 512 + 256);
    unsigned char* bp = (unsigned char*)(smem + 1024);

    const int j = tid >> 1, h = tid & 1;

    if (bidx < Bn) {
        // ---------------- FORWARD ----------------
        const int b = bidx;
        float Eh[64];
#pragma unroll
        for (int i = 0; i < 64; i++)
            Eh[i] = expf(trans[(h * 64 + i) * Kn + j]);

        const float* lg = g_logits + (size_t)b * Tn * Kn;
        wait_chunk(0, tid);

        float alpha = startT[j] + lg[j];
        float e_next = lg[Kn + j];

        for (int t = 1; t < Tn; t++) {
            float emit = e_next;
            if ((t & 63) == 63 && t + 1 < Tn) wait_chunk((t + 1) >> 6, tid);
            if (t + 1 < Tn) e_next = lg[(size_t)(t + 1) * Kn + j];
            int mt = mask[b * Tn + t];

            // block max of alpha
            float wm = alpha;
#pragma unroll
            for (int o = 16; o; o >>= 1)
                wm = fmaxf(wm, __shfl_xor_sync(FULL, wm, o));
            if ((tid & 31) == 0) shred[tid >> 5] = wm;
            __syncthreads();                       // S1
            float m = shred[0];
#pragma unroll
            for (int w = 1; w < 8; w++) m = fmaxf(m, shred[w]);

            float p = expf(alpha - m);
            if (h == 0) sh_s[j] = p;
            __syncthreads();                       // S2

            float s = 0.f;
            const float4* p4 = (const float4*)(sh_s + h * 64);
#pragma unroll
            for (int i4 = 0; i4 < 16; i4++) {
                float4 v = p4[i4];
                s += v.x * Eh[i4 * 4 + 0];
                s += v.y * Eh[i4 * 4 + 1];
                s += v.z * Eh[i4 * 4 + 2];
                s += v.w * Eh[i4 * 4 + 3];
            }
            s += __shfl_xor_sync(FULL, s, 1);
            float nxt = m + logf(s) + emit;
            alpha = (mt > 0) ? nxt : alpha;
        }

        // logZ
        __syncthreads();
        float v = alpha + endT[j];
        float wm = v;
#pragma unroll
        for (int o = 16; o; o >>= 1)
            wm = fmaxf(wm, __shfl_xor_sync(FULL, wm, o));
        if ((tid & 31) == 0) shred[tid >> 5] = wm;
        __syncthreads();
        float m = shred[0];
#pragma unroll
        for (int w = 1; w < 8; w++) m = fmaxf(m, shred[w]);
        __syncthreads();
        float pc = (h == 0) ? expf(v - m) : 0.f;
#pragma unroll
        for (int o = 16; o; o >>= 1)
            pc += __shfl_xor_sync(FULL, pc, o);
        if ((tid & 31) == 0) shred[tid >> 5] = pc;
        __syncthreads();
        float Z = 0.f;
#pragma unroll
        for (int w = 0; w < 8; w++) Z += shred[w];
        float logZ = m + logf(Z);
        __syncthreads();

        // path score
        float sc = 0.f;
        int msum = 0;
        for (int t = tid; t < Tn; t += 256) {
            msum += mask[b * Tn + t];
            if (t >= 1) {
                int cur  = labels[b * Tn + t];
                int prev = labels[b * Tn + t - 1];
                float mf = (float)mask[b * Tn + t];
                sc += (trans[prev * Kn + cur] + lg[(size_t)t * Kn + cur]) * mf;
            }
        }
#pragma unroll
        for (int o = 16; o; o >>= 1) {
            sc   += __shfl_xor_sync(FULL, sc, o);
            msum += __shfl_xor_sync(FULL, msum, o);
        }
        if ((tid & 31) == 0) { shred[tid >> 5] = sc; shredi[tid >> 5] = msum; }
        __syncthreads();
        if (tid == 0) {
            float S = 0.f; int Mc = 0;
#pragma unroll
            for (int w = 0; w < 8; w++) { S += shred[w]; Mc += shredi[w]; }
            int l0 = labels[b * Tn];
            S += startT[l0] + lg[l0];
            int last = labels[b * Tn + (Mc - 1)];
            S += endT[last];
            g_llh[b] = S - logZ;
        }
    } else {
        // ---------------- VITERBI ----------------
        const int b = bidx - Bn;
        float Th[64];
#pragma unroll
        for (int i = 0; i < 64; i++)
            Th[i] = trans[(h * 64 + i) * Kn + j];

        const float* lg = g_logits + (size_t)b * Tn * Kn;
        wait_chunk(0, tid);

        float sj = startT[j] + lg[j];
        if (h == 0) sh_s[j] = sj;
        float e_next = lg[Kn + j];
        __syncthreads();

        for (int t = 1; t < Tn; t++) {
            float emit = e_next;
            if ((t & 63) == 63 && t + 1 < Tn) wait_chunk((t + 1) >> 6, tid);
            if (t + 1 < Tn) e_next = lg[(size_t)(t + 1) * Kn + j];
            int mt = mask[b * Tn + t];

            float best = -3.4e38f;
            int arg = 0;
            const float4* s4 = (const float4*)(sh_s + h * 64);
#pragma unroll
            for (int i4 = 0; i4 < 16; i4++) {
                float4 v = s4[i4];
                float c0 = v.x + Th[i4 * 4 + 0];
                float c1 = v.y + Th[i4 * 4 + 1];
                float c2 = v.z + Th[i4 * 4 + 2];
                float c3 = v.w + Th[i4 * 4 + 3];
                if (c0 > best) { best = c0; arg = i4 * 4 + 0; }
                if (c1 > best) { best = c1; arg = i4 * 4 + 1; }
                if (c2 > best) { best = c2; arg = i4 * 4 + 2; }
                if (c3 > best) { best = c3; arg = i4 * 4 + 3; }
            }
            int ai = h * 64 + arg;
            float ob = __shfl_xor_sync(FULL, best, 1);
            int   oi = __shfl_xor_sync(FULL, ai, 1);
            // first-index-on-tie: lower-index candidate is the h==0 one
            float lb = (h == 0) ? best : ob;
            int   li = (h == 0) ? ai   : oi;
            float hb = (h == 0) ? ob   : best;
            int   hi = (h == 0) ? oi   : ai;
            float fb; int fa;
            if (hb > lb) { fb = hb; fa = hi; } else { fb = lb; fa = li; }

            float ns; int bpv;
            if (mt > 0) { ns = fb + emit; bpv = fa; }
            else        { ns = sj;        bpv = j;  }
            sj = ns;
            __syncthreads();                       // S1 (reads done)
            if (h == 0) {
                sh_s[j] = sj;
                bp[(size_t)(t - 1) * Kn + j] = (unsigned char)bpv;
            }
            __syncthreads();                       // S2 (writes visible)
        }

        if (h == 0) sh_s[j] = sj + endT[j];
        __syncthreads();
        if (tid == 0) {
            float bbest = sh_s[0];
            int btag = 0;
            for (int q = 1; q < Kn; q++) {
                float vv = sh_s[q];
                if (vv > bbest) { bbest = vv; btag = q; }
            }
            int tag = btag;
            out[b * Tn + (Tn - 1)] = (float)tag;
            for (int t = Tn - 2; t >= 0; t--) {
                tag = bp[(size_t)t * Kn + tag];
                out[b * Tn + t] = (float)tag;
            }
        }
    }
}

// ---------------------------------------------------------------------------
// loss = -mean(llh)
// ---------------------------------------------------------------------------
__global__ void loss_kernel(float* __restrict__ out)
{
    const unsigned FULL = 0xFFFFFFFFu;
    float v = (threadIdx.x < Bn) ? g_llh[threadIdx.x] : 0.f;
#pragma unroll
    for (int o = 16; o; o >>= 1) v += __shfl_xor_sync(FULL, v, o);
    if (threadIdx.x == 0) out[Bn * Tn] = -(v / (float)Bn);
}

extern "C" void kernel_launch(void* const* d_in, const int* in_sizes, int n_in,
                              void* d_out, int out_size)
{
    const float* hiddens = (const float*)d_in[0];
    const int*   mask    = (const int*)d_in[1];
    const int*   labels  = (const int*)d_in[2];
    const float* W       = (const float*)d_in[3];
    const float* bias    = (const float*)d_in[4];
    const float* startT  = (const float*)d_in[5];
    const float* endT    = (const float*)d_in[6];
    const float* trans   = (const float*)d_in[7];
    float* out = (float*)d_out;

    init_kernel<<<1, 32>>>();

    cudaFuncSetAttribute(fused_kernel, cudaFuncAttributeMaxDynamicSharedMemorySize,
                         SMEM_BYTES);
    fused_kernel<<<2 * Bn + NGEMM, 256, SMEM_BYTES>>>(
        hiddens, W, bias, mask, labels, startT, endT, trans, out);

    loss_kernel<<<1, 32>>>(out);
}